// round 1
// baseline (speedup 1.0000x reference)
#include <cuda_runtime.h>
#include <cstdint>

// Problem constants
#define BN_TOTAL 16384      // B*N = 4*4096
#define OUT1_OFF 1048576    // B*N*1*64
#define OUT2_OFF 4194304    // OUT1_OFF + B*N*3*64

// Scratch (device globals — the sanctioned no-alloc scratch mechanism)
__device__ __align__(16) float g_Mv[3 * 64 * 64];
__device__ __align__(16) float g_xv[BN_TOTAL * 9 * 64];
__device__ __align__(16) float g_skip[BN_TOTAL * 9 * 64];

__device__ __forceinline__ unsigned long long pack2(float lo, float hi) {
    unsigned long long r;
    asm("mov.b64 %0, {%1, %2};" : "=l"(r) : "f"(lo), "f"(hi));
    return r;
}
__device__ __forceinline__ void ffma2(unsigned long long &d, unsigned long long a, unsigned long long b) {
    asm("fma.rn.f32x2 %0, %1, %2, %3;" : "=l"(d) : "l"(a), "l"(b), "l"(d));
}

// ---------------------------------------------------------------------------
// Kernel M: Mv_d = Wconv_d @ Wv_d  (3 tiny 64x64x64 GEMMs)
// ---------------------------------------------------------------------------
__global__ void kernelM(const float* __restrict__ Wc0, const float* __restrict__ Wc1,
                        const float* __restrict__ Wc2, const float* __restrict__ Wv0,
                        const float* __restrict__ Wv1, const float* __restrict__ Wv2) {
    int d = blockIdx.x;
    const float* Wc = (d == 0) ? Wc0 : (d == 1 ? Wc1 : Wc2);
    const float* Wv = (d == 0) ? Wv0 : (d == 1 ? Wv1 : Wv2);
    for (int e = threadIdx.x; e < 4096; e += blockDim.x) {
        int c = e >> 6, co = e & 63;
        float s = 0.f;
        #pragma unroll 8
        for (int k = 0; k < 64; ++k) s = fmaf(Wc[c * 64 + k], Wv[k * 64 + co], s);
        g_Mv[d * 4096 + e] = s;
    }
}

// ---------------------------------------------------------------------------
// Kernel A: per-row dual GEMM.
//   rows = (b,n,mloc) of each degree tensor, 64 rows per block.
//   pass 0: xv   = (x*mask) @ Mv_deg   -> g_xv   (layout (bn, m0..8, 64))
//   pass 1: skip = (x*mask) @ Ws_deg   -> g_skip (same layout)
// f32x2 packed FMA microkernel: each thread computes 4 rows x 8 cols per pass.
// ---------------------------------------------------------------------------
__global__ __launch_bounds__(128) void kernelA(
    const float* __restrict__ x0, const float* __restrict__ x1, const float* __restrict__ x2,
    const float* __restrict__ mask,
    const float* __restrict__ Ws0, const float* __restrict__ Ws1, const float* __restrict__ Ws2)
{
    __shared__ __align__(16) float sW[64 * 64];
    __shared__ __align__(16) float sX[64 * 65];   // padded stride 65: conflict-free col reads

    int bx = blockIdx.x, tid = threadIdx.x;
    int tile, md, moff;
    const float *x, *Ws, *Wm;
    if (bx < 256)       { tile = bx;        x = x0; Ws = Ws0; Wm = g_Mv;        md = 1; moff = 0; }
    else if (bx < 1024) { tile = bx - 256;  x = x1; Ws = Ws1; Wm = g_Mv + 4096; md = 3; moff = 1; }
    else                { tile = bx - 1024; x = x2; Ws = Ws2; Wm = g_Mv + 8192; md = 5; moff = 4; }
    int row0 = tile * 64;

    // Load x tile (64 rows x 64 cols, contiguous 16KB) with source mask applied
    const float* xb = x + (size_t)row0 * 64;
    #pragma unroll
    for (int it = 0; it < 8; ++it) {
        int i = tid * 4 + it * 512;
        int r = i >> 6, c = i & 63;
        float4 v = *(const float4*)(xb + i);
        float mk = mask[(row0 + r) / md];
        sX[r * 65 + c + 0] = v.x * mk;
        sX[r * 65 + c + 1] = v.y * mk;
        sX[r * 65 + c + 2] = v.z * mk;
        sX[r * 65 + c + 3] = v.w * mk;
    }
    // Load Mv for pass 0
    #pragma unroll
    for (int it = 0; it < 8; ++it) {
        int i = tid * 4 + it * 512;
        *(float4*)(sW + i) = *(const float4*)(Wm + i);
    }
    __syncthreads();

    int ct = tid & 7, rt = tid >> 3;     // 8 col-groups x 16 row-groups
    int c0 = ct * 8, rl = rt * 4;

    #pragma unroll 1
    for (int pass = 0; pass < 2; ++pass) {
        unsigned long long acc[4][4];
        #pragma unroll
        for (int i = 0; i < 4; i++)
            #pragma unroll
            for (int j = 0; j < 4; j++) acc[i][j] = 0ull;

        #pragma unroll 4
        for (int k = 0; k < 64; ++k) {
            unsigned long long a2[4], b2[4];
            #pragma unroll
            for (int i = 0; i < 4; i++) {
                float a = sX[(rl + i) * 65 + k];
                a2[i] = pack2(a, a);
            }
            float4 bA = *(const float4*)(sW + k * 64 + c0);
            float4 bB = *(const float4*)(sW + k * 64 + c0 + 4);
            b2[0] = pack2(bA.x, bA.y); b2[1] = pack2(bA.z, bA.w);
            b2[2] = pack2(bB.x, bB.y); b2[3] = pack2(bB.z, bB.w);
            #pragma unroll
            for (int i = 0; i < 4; i++)
                #pragma unroll
                for (int j = 0; j < 4; j++) ffma2(acc[i][j], a2[i], b2[j]);
        }

        float* dstbase = (pass == 0) ? g_xv : g_skip;
        #pragma unroll
        for (int i = 0; i < 4; i++) {
            int r = row0 + rl + i;
            int bn = r / md, mloc = r - bn * md;
            float* dst = dstbase + ((bn * 9 + moff + mloc) * 64 + c0);
            #pragma unroll
            for (int j = 0; j < 4; j++) *(float2*)(dst + 2 * j) = *(float2*)&acc[i][j];
        }

        if (pass == 0) {
            __syncthreads();       // all reads of Mv done
            #pragma unroll
            for (int it = 0; it < 8; ++it) {
                int i = tid * 4 + it * 512;
                *(float4*)(sW + i) = *(const float4*)(Ws + i);
            }
            __syncthreads();
        }
    }
}

// ---------------------------------------------------------------------------
// Kernel B: one block per point (b,n). 288 threads = 9 warps (one per m-row).
//   1) warp 0: compute w[k], ballot-compact the ~20% nonzero neighbors
//   2) weighted gather-accumulate of g_xv rows over nonzero neighbors only
//   3) per-(deg,co) normalization + nonlinearity factors
//   4) out = a + skip, * mask, scattered to the three concatenated outputs
// ---------------------------------------------------------------------------
__global__ __launch_bounds__(288) void kernelB(
    const float* __restrict__ points, const int* __restrict__ pidx,
    const float* __restrict__ mask, float* __restrict__ out)
{
    __shared__ float sw[32];
    __shared__ int   srow[32];
    __shared__ int   snnz;
    __shared__ __align__(8) float vbuf[576];
    __shared__ __align__(8) float fbuf[192];

    int bn = blockIdx.x;
    int tid = threadIdx.x;

    if (tid < 32) {
        int idx  = pidx[bn * 32 + tid];
        int b    = bn >> 12;                 // N = 4096
        int prow = (b << 12) + idx;
        float cx = points[bn * 3 + 0], cy = points[bn * 3 + 1], cz = points[bn * 3 + 2];
        float dx = points[prow * 3 + 0] - cx;
        float dy = points[prow * 3 + 1] - cy;
        float dz = points[prow * 3 + 2] - cz;
        float r  = sqrtf(fmaf(dx, dx, fmaf(dy, dy, fmaf(dz, dz, 1e-12f))));
        float w  = 1.0f - r / 0.4f;
        bool act = w > 0.0f;
        unsigned bal = __ballot_sync(0xffffffffu, act);
        int pos = __popc(bal & ((1u << tid) - 1u));
        if (act) { sw[pos] = w; srow[pos] = prow * 576; }
        if (tid == 0) snnz = __popc(bal);
    }
    __syncthreads();

    int m = tid >> 5, j = tid & 31;
    int off = m * 64 + j * 2;
    int nnz = snnz;

    float ax = 0.f, ay = 0.f;
    int i = 0;
    for (; i + 4 <= nnz; i += 4) {
        float w0 = sw[i + 0], w1 = sw[i + 1], w2 = sw[i + 2], w3 = sw[i + 3];
        float2 p0 = *(const float2*)(g_xv + srow[i + 0] + off);
        float2 p1 = *(const float2*)(g_xv + srow[i + 1] + off);
        float2 p2 = *(const float2*)(g_xv + srow[i + 2] + off);
        float2 p3 = *(const float2*)(g_xv + srow[i + 3] + off);
        ax = fmaf(w0, p0.x, ax); ay = fmaf(w0, p0.y, ay);
        ax = fmaf(w1, p1.x, ax); ay = fmaf(w1, p1.y, ay);
        ax = fmaf(w2, p2.x, ax); ay = fmaf(w2, p2.y, ay);
        ax = fmaf(w3, p3.x, ax); ay = fmaf(w3, p3.y, ay);
    }
    for (; i < nnz; ++i) {
        float w0 = sw[i];
        float2 p0 = *(const float2*)(g_xv + srow[i] + off);
        ax = fmaf(w0, p0.x, ax); ay = fmaf(w0, p0.y, ay);
    }
    vbuf[off] = ax; vbuf[off + 1] = ay;
    __syncthreads();

    if (tid < 192) {
        int d  = tid >> 6, co = tid & 63;
        int m0 = (d == 0) ? 0 : (d == 1 ? 1 : 4);
        int mc = (d == 0) ? 1 : (d == 1 ? 3 : 5);
        float S = 0.f;
        for (int mm = 0; mm < mc; ++mm) {
            float v = vbuf[(m0 + mm) * 64 + co];
            S = fmaf(v, v, S);
        }
        float scale = rsqrtf(S + 0.01f);
        float f = scale;
        if (d > 0) {
            float S2 = S * scale * scale;             // = sum of normalized v^2
            float nn = sqrtf(S2 + 0.01f);
            f = scale * (1.0f / (1.0f + __expf(-nn)));
        }
        fbuf[tid] = f;
    }
    __syncthreads();

    float mk = mask[bn];
    int d = (m == 0) ? 0 : (m < 4 ? 1 : 2);
    float2 f2 = *(const float2*)&fbuf[d * 64 + 2 * j];
    float a0 = ax * f2.x, a1 = ay * f2.y;
    if (m == 0) { a0 = fmaxf(a0, 0.f); a1 = fmaxf(a1, 0.f); }

    float2 sk = *(const float2*)(g_skip + bn * 576 + off);
    float o0 = (a0 + sk.x) * mk;
    float o1 = (a1 + sk.y) * mk;

    float* op;
    if (m == 0)      op = out + bn * 64 + 2 * j;
    else if (m < 4)  op = out + OUT1_OFF + (bn * 3 + (m - 1)) * 64 + 2 * j;
    else             op = out + OUT2_OFF + (bn * 5 + (m - 4)) * 64 + 2 * j;
    *(float2*)op = make_float2(o0, o1);
}

// ---------------------------------------------------------------------------
extern "C" void kernel_launch(void* const* d_in, const int* in_sizes, int n_in,
                              void* d_out, int out_size) {
    const float* x0     = (const float*)d_in[0];
    const float* x1     = (const float*)d_in[1];
    const float* x2     = (const float*)d_in[2];
    const float* points = (const float*)d_in[3];
    const int*   pidx   = (const int*)  d_in[4];
    const float* mask   = (const float*)d_in[5];
    const float* Wc0    = (const float*)d_in[6];
    const float* Wc1    = (const float*)d_in[7];
    const float* Wc2    = (const float*)d_in[8];
    const float* Wv0    = (const float*)d_in[9];
    const float* Wv1    = (const float*)d_in[10];
    const float* Wv2    = (const float*)d_in[11];
    const float* Ws0    = (const float*)d_in[12];
    const float* Ws1    = (const float*)d_in[13];
    const float* Ws2    = (const float*)d_in[14];
    float* out = (float*)d_out;

    kernelM<<<3, 256>>>(Wc0, Wc1, Wc2, Wv0, Wv1, Wv2);
    kernelA<<<2304, 128>>>(x0, x1, x2, mask, Ws0, Ws1, Ws2);
    kernelB<<<16384, 288>>>(points, pidx, mask, out);
}

// round 3
// speedup vs baseline: 1.2242x; 1.2242x over previous
#include <cuda_runtime.h>
#include <cuda_fp16.h>
#include <cstdint>

// Problem constants
#define BN_TOTAL 16384      // B*N = 4*4096
#define OUT1_OFF 1048576    // B*N*1*64
#define OUT2_OFF 4194304    // OUT1_OFF + B*N*3*64

// Scratch (device globals — the sanctioned no-alloc scratch mechanism)
__device__ __align__(16) float  g_Mv[3 * 64 * 64];
__device__ __align__(16) __half g_xvh[BN_TOTAL * 9 * 64];   // fp16 gathered tensor
__device__ __align__(16) float  g_skip[BN_TOTAL * 9 * 64];  // fp32 skip path

__device__ __forceinline__ unsigned long long pack2(float lo, float hi) {
    unsigned long long r;
    asm("mov.b64 %0, {%1, %2};" : "=l"(r) : "f"(lo), "f"(hi));
    return r;
}
__device__ __forceinline__ void ffma2(unsigned long long &d, unsigned long long a, unsigned long long b) {
    asm("fma.rn.f32x2 %0, %1, %2, %3;" : "=l"(d) : "l"(a), "l"(b), "l"(d));
}

// ---------------------------------------------------------------------------
// Kernel M: Mv_d = Wconv_d @ Wv_d  (3 tiny 64x64x64 GEMMs)
// smem-staged, 1024 threads/block, 4 outputs/thread -> latency ~= 2 tile loads
// ---------------------------------------------------------------------------
__global__ __launch_bounds__(1024) void kernelM(
    const float* __restrict__ Wc0, const float* __restrict__ Wc1,
    const float* __restrict__ Wc2, const float* __restrict__ Wv0,
    const float* __restrict__ Wv1, const float* __restrict__ Wv2)
{
    __shared__ __align__(16) float sWc[64 * 64];
    __shared__ __align__(16) float sWv[64 * 64];
    int d = blockIdx.x;
    const float* Wc = (d == 0) ? Wc0 : (d == 1 ? Wc1 : Wc2);
    const float* Wv = (d == 0) ? Wv0 : (d == 1 ? Wv1 : Wv2);
    int tid = threadIdx.x;
    *(float4*)(sWc + tid * 4) = *(const float4*)(Wc + tid * 4);
    *(float4*)(sWv + tid * 4) = *(const float4*)(Wv + tid * 4);
    __syncthreads();

    int c = tid >> 4, g = (tid & 15) * 4;
    float4 acc = make_float4(0.f, 0.f, 0.f, 0.f);
    #pragma unroll 8
    for (int k = 0; k < 64; ++k) {
        float a = sWc[c * 64 + k];
        float4 b = *(const float4*)(sWv + k * 64 + g);
        acc.x = fmaf(a, b.x, acc.x);
        acc.y = fmaf(a, b.y, acc.y);
        acc.z = fmaf(a, b.z, acc.z);
        acc.w = fmaf(a, b.w, acc.w);
    }
    *(float4*)(g_Mv + d * 4096 + c * 64 + g) = acc;
}

// ---------------------------------------------------------------------------
// Kernel A: per-row dual GEMM.
//   pass 0: xv   = (x*mask) @ Mv_deg   -> g_xvh  (fp16, layout (bn, m0..8, 64))
//   pass 1: skip = (x*mask) @ Ws_deg   -> g_skip (fp32, same layout)
// f32x2 packed FMA microkernel: each thread computes 4 rows x 8 cols per pass.
// ---------------------------------------------------------------------------
__global__ __launch_bounds__(128) void kernelA(
    const float* __restrict__ x0, const float* __restrict__ x1, const float* __restrict__ x2,
    const float* __restrict__ mask,
    const float* __restrict__ Ws0, const float* __restrict__ Ws1, const float* __restrict__ Ws2)
{
    __shared__ __align__(16) float sW[64 * 64];
    __shared__ __align__(16) float sX[64 * 65];   // padded stride 65: conflict-free col reads

    int bx = blockIdx.x, tid = threadIdx.x;
    int tile, md, moff;
    const float *x, *Ws, *Wm;
    if (bx < 256)       { tile = bx;        x = x0; Ws = Ws0; Wm = g_Mv;        md = 1; moff = 0; }
    else if (bx < 1024) { tile = bx - 256;  x = x1; Ws = Ws1; Wm = g_Mv + 4096; md = 3; moff = 1; }
    else                { tile = bx - 1024; x = x2; Ws = Ws2; Wm = g_Mv + 8192; md = 5; moff = 4; }
    int row0 = tile * 64;

    // Load x tile (64 rows x 64 cols, contiguous 16KB) with source mask applied
    const float* xb = x + (size_t)row0 * 64;
    #pragma unroll
    for (int it = 0; it < 8; ++it) {
        int i = tid * 4 + it * 512;
        int r = i >> 6, c = i & 63;
        float4 v = *(const float4*)(xb + i);
        float mk = mask[(row0 + r) / md];
        sX[r * 65 + c + 0] = v.x * mk;
        sX[r * 65 + c + 1] = v.y * mk;
        sX[r * 65 + c + 2] = v.z * mk;
        sX[r * 65 + c + 3] = v.w * mk;
    }
    // Load Mv for pass 0
    #pragma unroll
    for (int it = 0; it < 8; ++it) {
        int i = tid * 4 + it * 512;
        *(float4*)(sW + i) = *(const float4*)(Wm + i);
    }
    __syncthreads();

    int ct = tid & 7, rt = tid >> 3;     // 8 col-groups x 16 row-groups
    int c0 = ct * 8, rl = rt * 4;

    #pragma unroll 1
    for (int pass = 0; pass < 2; ++pass) {
        unsigned long long acc[4][4];
        #pragma unroll
        for (int i = 0; i < 4; i++)
            #pragma unroll
            for (int j = 0; j < 4; j++) acc[i][j] = 0ull;

        #pragma unroll 4
        for (int k = 0; k < 64; ++k) {
            unsigned long long a2[4], b2[4];
            #pragma unroll
            for (int i = 0; i < 4; i++) {
                float a = sX[(rl + i) * 65 + k];
                a2[i] = pack2(a, a);
            }
            float4 bA = *(const float4*)(sW + k * 64 + c0);
            float4 bB = *(const float4*)(sW + k * 64 + c0 + 4);
            b2[0] = pack2(bA.x, bA.y); b2[1] = pack2(bA.z, bA.w);
            b2[2] = pack2(bB.x, bB.y); b2[3] = pack2(bB.z, bB.w);
            #pragma unroll
            for (int i = 0; i < 4; i++)
                #pragma unroll
                for (int j = 0; j < 4; j++) ffma2(acc[i][j], a2[i], b2[j]);
        }

        #pragma unroll
        for (int i = 0; i < 4; i++) {
            int r = row0 + rl + i;
            int bn = r / md, mloc = r - bn * md;
            int rowoff = (bn * 9 + moff + mloc) * 64 + c0;
            if (pass == 0) {
                __half2 h[4];
                #pragma unroll
                for (int j = 0; j < 4; j++) {
                    float2 f = *(float2*)&acc[i][j];
                    h[j] = __floats2half2_rn(f.x, f.y);
                }
                *(uint4*)(g_xvh + rowoff) = *(uint4*)h;
            } else {
                float* dst = g_skip + rowoff;
                #pragma unroll
                for (int j = 0; j < 4; j++) *(float2*)(dst + 2 * j) = *(float2*)&acc[i][j];
            }
        }

        if (pass == 0) {
            __syncthreads();       // all reads of Mv done
            #pragma unroll
            for (int it = 0; it < 8; ++it) {
                int i = tid * 4 + it * 512;
                *(float4*)(sW + i) = *(const float4*)(Ws + i);
            }
            __syncthreads();
        }
    }
}

// ---------------------------------------------------------------------------
// Kernel B: one block per point (b,n). 288 threads = 9 warps (one per m-row).
//   1) warp 0: compute w[k], ballot-compact the ~20% nonzero neighbors
//   2) weighted gather-accumulate of g_xvh rows (fp16, 128B/line per warp)
//   3) per-(deg,co) normalization + nonlinearity factors
//   4) out = a + skip, * mask, scattered to the three concatenated outputs
// ---------------------------------------------------------------------------
__global__ __launch_bounds__(288) void kernelB(
    const float* __restrict__ points, const int* __restrict__ pidx,
    const float* __restrict__ mask, float* __restrict__ out)
{
    __shared__ float sw[32];
    __shared__ int   srow[32];
    __shared__ int   snnz;
    __shared__ __align__(8) float vbuf[576];
    __shared__ __align__(8) float fbuf[192];

    int bn = blockIdx.x;
    int tid = threadIdx.x;

    if (tid < 32) {
        int idx  = pidx[bn * 32 + tid];
        int b    = bn >> 12;                 // N = 4096
        int prow = (b << 12) + idx;
        float cx = points[bn * 3 + 0], cy = points[bn * 3 + 1], cz = points[bn * 3 + 2];
        float dx = points[prow * 3 + 0] - cx;
        float dy = points[prow * 3 + 1] - cy;
        float dz = points[prow * 3 + 2] - cz;
        float r  = sqrtf(fmaf(dx, dx, fmaf(dy, dy, fmaf(dz, dz, 1e-12f))));
        float w  = 1.0f - r / 0.4f;
        bool act = w > 0.0f;
        unsigned bal = __ballot_sync(0xffffffffu, act);
        int pos = __popc(bal & ((1u << tid) - 1u));
        if (act) { sw[pos] = w; srow[pos] = prow * 576; }
        if (tid == 0) snnz = __popc(bal);
    }
    __syncthreads();

    int m = tid >> 5, j = tid & 31;
    int off = m * 64 + j * 2;
    int nnz = snnz;

    float ax = 0.f, ay = 0.f;
    int i = 0;
    for (; i + 4 <= nnz; i += 4) {
        float w0 = sw[i + 0], w1 = sw[i + 1], w2 = sw[i + 2], w3 = sw[i + 3];
        float2 p0 = __half22float2(*(const __half2*)(g_xvh + srow[i + 0] + off));
        float2 p1 = __half22float2(*(const __half2*)(g_xvh + srow[i + 1] + off));
        float2 p2 = __half22float2(*(const __half2*)(g_xvh + srow[i + 2] + off));
        float2 p3 = __half22float2(*(const __half2*)(g_xvh + srow[i + 3] + off));
        ax = fmaf(w0, p0.x, ax); ay = fmaf(w0, p0.y, ay);
        ax = fmaf(w1, p1.x, ax); ay = fmaf(w1, p1.y, ay);
        ax = fmaf(w2, p2.x, ax); ay = fmaf(w2, p2.y, ay);
        ax = fmaf(w3, p3.x, ax); ay = fmaf(w3, p3.y, ay);
    }
    for (; i < nnz; ++i) {
        float w0 = sw[i];
        float2 p0 = __half22float2(*(const __half2*)(g_xvh + srow[i] + off));
        ax = fmaf(w0, p0.x, ax); ay = fmaf(w0, p0.y, ay);
    }
    vbuf[off] = ax; vbuf[off + 1] = ay;
    __syncthreads();

    if (tid < 192) {
        int d  = tid >> 6, co = tid & 63;
        int m0 = (d == 0) ? 0 : (d == 1 ? 1 : 4);
        int mc = (d == 0) ? 1 : (d == 1 ? 3 : 5);
        float S = 0.f;
        for (int mm = 0; mm < mc; ++mm) {
            float v = vbuf[(m0 + mm) * 64 + co];
            S = fmaf(v, v, S);
        }
        float scale = rsqrtf(S + 0.01f);
        float f = scale;
        if (d > 0) {
            float S2 = S * scale * scale;             // = sum of normalized v^2
            float nn = sqrtf(S2 + 0.01f);
            f = scale * (1.0f / (1.0f + __expf(-nn)));
        }
        fbuf[tid] = f;
    }
    __syncthreads();

    float mk = mask[bn];
    int d = (m == 0) ? 0 : (m < 4 ? 1 : 2);
    float2 f2 = *(const float2*)&fbuf[d * 64 + 2 * j];
    float a0 = ax * f2.x, a1 = ay * f2.y;
    if (m == 0) { a0 = fmaxf(a0, 0.f); a1 = fmaxf(a1, 0.f); }

    float2 sk = *(const float2*)(g_skip + bn * 576 + off);
    float o0 = (a0 + sk.x) * mk;
    float o1 = (a1 + sk.y) * mk;

    float* op;
    if (m == 0)      op = out + bn * 64 + 2 * j;
    else if (m < 4)  op = out + OUT1_OFF + (bn * 3 + (m - 1)) * 64 + 2 * j;
    else             op = out + OUT2_OFF + (bn * 5 + (m - 4)) * 64 + 2 * j;
    *(float2*)op = make_float2(o0, o1);
}

// ---------------------------------------------------------------------------
extern "C" void kernel_launch(void* const* d_in, const int* in_sizes, int n_in,
                              void* d_out, int out_size) {
    const float* x0     = (const float*)d_in[0];
    const float* x1     = (const float*)d_in[1];
    const float* x2     = (const float*)d_in[2];
    const float* points = (const float*)d_in[3];
    const int*   pidx   = (const int*)  d_in[4];
    const float* mask   = (const float*)d_in[5];
    const float* Wc0    = (const float*)d_in[6];
    const float* Wc1    = (const float*)d_in[7];
    const float* Wc2    = (const float*)d_in[8];
    const float* Wv0    = (const float*)d_in[9];
    const float* Wv1    = (const float*)d_in[10];
    const float* Wv2    = (const float*)d_in[11];
    const float* Ws0    = (const float*)d_in[12];
    const float* Ws1    = (const float*)d_in[13];
    const float* Ws2    = (const float*)d_in[14];
    float* out = (float*)d_out;

    kernelM<<<3, 1024>>>(Wc0, Wc1, Wc2, Wv0, Wv1, Wv2);
    kernelA<<<2304, 128>>>(x0, x1, x2, mask, Ws0, Ws1, Ws2);
    kernelB<<<16384, 288>>>(points, pidx, mask, out);
}

// round 5
// speedup vs baseline: 1.4783x; 1.2075x over previous
#include <cuda_runtime.h>
#include <cuda_fp16.h>
#include <cstdint>

// Problem constants
#define BN_TOTAL 16384      // B*N = 4*4096
#define OUT1_OFF 1048576    // B*N*1*64
#define OUT2_OFF 4194304    // OUT1_OFF + B*N*3*64

// Scratch (device globals — the sanctioned no-alloc scratch mechanism)
__device__ __align__(16) float  g_Mv[3 * 64 * 64];
__device__ __align__(16) __half g_xvh[BN_TOTAL * 9 * 64];   // fp16 gathered tensor
__device__ __align__(16) float  g_skip[BN_TOTAL * 9 * 64];  // fp32 skip path

__device__ __forceinline__ void ffma2(unsigned long long &d, unsigned long long a, unsigned long long b) {
    asm("fma.rn.f32x2 %0, %1, %2, %3;" : "=l"(d) : "l"(a), "l"(b), "l"(d));
}
__device__ __forceinline__ float2 unpk(unsigned long long v) {
    float2 f;
    asm("mov.b64 {%0, %1}, %2;" : "=f"(f.x), "=f"(f.y) : "l"(v));
    return f;
}

// ---------------------------------------------------------------------------
// Kernel M: Mv_d = Wconv_d @ Wv_d.  12 blocks = 3 degrees x 4 col-slices(16).
// smem: Wc full (padded stride 65 -> conflict-free a loads), Wv 16-col slice.
// ---------------------------------------------------------------------------
__global__ __launch_bounds__(256) void kernelM(
    const float* __restrict__ Wc0, const float* __restrict__ Wc1,
    const float* __restrict__ Wc2, const float* __restrict__ Wv0,
    const float* __restrict__ Wv1, const float* __restrict__ Wv2)
{
    __shared__ float sWc[64 * 65];
    __shared__ __align__(16) float sWvS[64 * 16];
    int d = blockIdx.x >> 2, sl = blockIdx.x & 3;
    int g0 = sl * 16;
    const float* Wc = (d == 0) ? Wc0 : (d == 1 ? Wc1 : Wc2);
    const float* Wv = (d == 0) ? Wv0 : (d == 1 ? Wv1 : Wv2);
    int tid = threadIdx.x;

    #pragma unroll
    for (int it = 0; it < 16; ++it) {           // Wc: 4096 scalars, padded store
        int i = tid + it * 256;
        int k = i & 63, c = i >> 6;
        sWc[c * 65 + k] = Wc[i];
    }
    {
        int i = tid * 4;                         // Wv slice: 1024 floats
        int k = i >> 4, cc = i & 15;
        *(float4*)(sWvS + k * 16 + cc) = *(const float4*)(Wv + k * 64 + g0 + cc);
    }
    __syncthreads();

    int c = tid & 63, cg = (tid >> 6) * 4;
    float4 acc = make_float4(0.f, 0.f, 0.f, 0.f);
    #pragma unroll 8
    for (int k = 0; k < 64; ++k) {
        float a = sWc[c * 65 + k];
        float4 b = *(const float4*)(sWvS + k * 16 + cg);
        acc.x = fmaf(a, b.x, acc.x);
        acc.y = fmaf(a, b.y, acc.y);
        acc.z = fmaf(a, b.z, acc.z);
        acc.w = fmaf(a, b.w, acc.w);
    }
    *(float4*)(g_Mv + d * 4096 + c * 64 + g0 + cg) = acc;
}

// ---------------------------------------------------------------------------
// Kernel A: fused dual GEMM per 64-row tile.
//   xv   = (x*mask) @ Mv_deg -> g_xvh (fp16)
//   skip = (x*mask) @ Ws_deg -> g_skip (fp32)
// k-pair f32x2 microkernel: acc pairs span two k values; a from LDS.128 of
// sX, b from LDS.128 of transposed W -> no pack MOVs. Both matrices share
// every a-load. 256 thr, per-thread tile 4 rows x 4 cols (stride 16) x 2 mats.
// Dynamic smem: sX(64x68) + sWmT(64x68) + sWsT(64x68) = 52224 B.
// ---------------------------------------------------------------------------
#define ASTR 68
__global__ __launch_bounds__(256) void kernelA(
    const float* __restrict__ x0, const float* __restrict__ x1, const float* __restrict__ x2,
    const float* __restrict__ mask,
    const float* __restrict__ Ws0, const float* __restrict__ Ws1, const float* __restrict__ Ws2)
{
    extern __shared__ __align__(16) float smem[];
    float* sX   = smem;                 // [64][ASTR] row r, col k
    float* sWmT = smem + 64 * ASTR;     // [64][ASTR] row c, col k (transposed!)
    float* sWsT = smem + 2 * 64 * ASTR;

    int bx = blockIdx.x, tid = threadIdx.x;
    int tile, md, moff;
    const float *x, *Ws, *Wm;
    if (bx < 256)       { tile = bx;        x = x0; Ws = Ws0; Wm = g_Mv;        md = 1; moff = 0; }
    else if (bx < 1024) { tile = bx - 256;  x = x1; Ws = Ws1; Wm = g_Mv + 4096; md = 3; moff = 1; }
    else                { tile = bx - 1024; x = x2; Ws = Ws2; Wm = g_Mv + 8192; md = 5; moff = 4; }
    int row0 = tile * 64;

    // x tile with mask applied (vectorized, 4 iters)
    const float* xb = x + (size_t)row0 * 64;
    #pragma unroll
    for (int it = 0; it < 4; ++it) {
        int i = tid * 4 + it * 1024;
        int r = i >> 6, c = i & 63;
        float4 v = *(const float4*)(xb + i);
        float mk = mask[(row0 + r) / md];
        float* dst = sX + r * ASTR + c;
        dst[0] = v.x * mk; dst[1] = v.y * mk; dst[2] = v.z * mk; dst[3] = v.w * mk;
    }
    // Transposed weight loads (scalar; coalesced LDG, minor STS conflicts)
    #pragma unroll
    for (int it = 0; it < 16; ++it) {
        int i = tid + it * 256;
        int k = i >> 6, c = i & 63;
        sWmT[c * ASTR + k] = Wm[i];
        sWsT[c * ASTR + k] = Ws[i];
    }
    __syncthreads();

    int rt = tid >> 4, ct = tid & 15;   // 16 row-groups x 16 col-threads
    int rl = rt * 4;                    // 4 rows; cols: ct, ct+16, ct+32, ct+48

    unsigned long long accM[4][4], accS[4][4];
    #pragma unroll
    for (int i = 0; i < 4; i++)
        #pragma unroll
        for (int j = 0; j < 4; j++) { accM[i][j] = 0ull; accS[i][j] = 0ull; }

    #pragma unroll 4
    for (int kc = 0; kc < 64; kc += 4) {
        ulonglong2 aP[4], bM[4], bS[4];
        #pragma unroll
        for (int i = 0; i < 4; i++)
            aP[i] = *(const ulonglong2*)(sX + (rl + i) * ASTR + kc);
        #pragma unroll
        for (int j = 0; j < 4; j++) {
            bM[j] = *(const ulonglong2*)(sWmT + (ct + 16 * j) * ASTR + kc);
            bS[j] = *(const ulonglong2*)(sWsT + (ct + 16 * j) * ASTR + kc);
        }
        #pragma unroll
        for (int i = 0; i < 4; i++)
            #pragma unroll
            for (int j = 0; j < 4; j++) {
                ffma2(accM[i][j], aP[i].x, bM[j].x);
                ffma2(accM[i][j], aP[i].y, bM[j].y);
                ffma2(accS[i][j], aP[i].x, bS[j].x);
                ffma2(accS[i][j], aP[i].y, bS[j].y);
            }
    }

    // Epilogue: reduce pair halves, store fp16 xv + fp32 skip
    #pragma unroll
    for (int i = 0; i < 4; i++) {
        int r = row0 + rl + i;
        int bn = r / md, mloc = r - bn * md;
        int base = (bn * 9 + moff + mloc) * 64;
        #pragma unroll
        for (int j = 0; j < 4; j++) {
            int c = ct + 16 * j;
            float2 m = unpk(accM[i][j]);
            float2 s = unpk(accS[i][j]);
            g_xvh[base + c]  = __float2half_rn(m.x + m.y);
            g_skip[base + c] = s.x + s.y;
        }
    }
}

// ---------------------------------------------------------------------------
// Kernel B: one block per point (b,n). 288 threads = 9 warps (one per m-row).
//   1) warp 0: compute w[k], ballot-compact the ~20% nonzero neighbors
//   2) weighted gather-accumulate of g_xvh rows (fp16, 128B/line per warp)
//   3) per-(deg,co) normalization + nonlinearity factors
//   4) out = a + skip, * mask, scattered to the three concatenated outputs
// ---------------------------------------------------------------------------
__global__ __launch_bounds__(288) void kernelB(
    const float* __restrict__ points, const int* __restrict__ pidx,
    const float* __restrict__ mask, float* __restrict__ out)
{
    __shared__ float sw[32];
    __shared__ int   srow[32];
    __shared__ int   snnz;
    __shared__ __align__(8) float vbuf[576];
    __shared__ __align__(8) float fbuf[192];

    int bn = blockIdx.x;
    int tid = threadIdx.x;

    if (tid < 32) {
        int idx  = pidx[bn * 32 + tid];
        int b    = bn >> 12;                 // N = 4096
        int prow = (b << 12) + idx;
        float cx = points[bn * 3 + 0], cy = points[bn * 3 + 1], cz = points[bn * 3 + 2];
        float dx = points[prow * 3 + 0] - cx;
        float dy = points[prow * 3 + 1] - cy;
        float dz = points[prow * 3 + 2] - cz;
        float r  = sqrtf(fmaf(dx, dx, fmaf(dy, dy, fmaf(dz, dz, 1e-12f))));
        float w  = 1.0f - r / 0.4f;
        bool act = w > 0.0f;
        unsigned bal = __ballot_sync(0xffffffffu, act);
        int pos = __popc(bal & ((1u << tid) - 1u));
        if (act) { sw[pos] = w; srow[pos] = prow * 576; }
        if (tid == 0) snnz = __popc(bal);
    }
    __syncthreads();

    int m = tid >> 5, j = tid & 31;
    int off = m * 64 + j * 2;
    int nnz = snnz;

    float ax = 0.f, ay = 0.f;
    int i = 0;
    for (; i + 4 <= nnz; i += 4) {
        float w0 = sw[i + 0], w1 = sw[i + 1], w2 = sw[i + 2], w3 = sw[i + 3];
        float2 p0 = __half22float2(*(const __half2*)(g_xvh + srow[i + 0] + off));
        float2 p1 = __half22float2(*(const __half2*)(g_xvh + srow[i + 1] + off));
        float2 p2 = __half22float2(*(const __half2*)(g_xvh + srow[i + 2] + off));
        float2 p3 = __half22float2(*(const __half2*)(g_xvh + srow[i + 3] + off));
        ax = fmaf(w0, p0.x, ax); ay = fmaf(w0, p0.y, ay);
        ax = fmaf(w1, p1.x, ax); ay = fmaf(w1, p1.y, ay);
        ax = fmaf(w2, p2.x, ax); ay = fmaf(w2, p2.y, ay);
        ax = fmaf(w3, p3.x, ax); ay = fmaf(w3, p3.y, ay);
    }
    for (; i < nnz; ++i) {
        float w0 = sw[i];
        float2 p0 = __half22float2(*(const __half2*)(g_xvh + srow[i] + off));
        ax = fmaf(w0, p0.x, ax); ay = fmaf(w0, p0.y, ay);
    }
    vbuf[off] = ax; vbuf[off + 1] = ay;
    __syncthreads();

    if (tid < 192) {
        int d  = tid >> 6, co = tid & 63;
        int m0 = (d == 0) ? 0 : (d == 1 ? 1 : 4);
        int mc = (d == 0) ? 1 : (d == 1 ? 3 : 5);
        float S = 0.f;
        for (int mm = 0; mm < mc; ++mm) {
            float v = vbuf[(m0 + mm) * 64 + co];
            S = fmaf(v, v, S);
        }
        float scale = rsqrtf(S + 0.01f);
        float f = scale;
        if (d > 0) {
            float S2 = S * scale * scale;             // = sum of normalized v^2
            float nn = sqrtf(S2 + 0.01f);
            f = scale * (1.0f / (1.0f + __expf(-nn)));
        }
        fbuf[tid] = f;
    }
    __syncthreads();

    float mk = mask[bn];
    int d = (m == 0) ? 0 : (m < 4 ? 1 : 2);
    float2 f2 = *(const float2*)&fbuf[d * 64 + 2 * j];
    float a0 = ax * f2.x, a1 = ay * f2.y;
    if (m == 0) { a0 = fmaxf(a0, 0.f); a1 = fmaxf(a1, 0.f); }

    float2 sk = *(const float2*)(g_skip + bn * 576 + off);
    float o0 = (a0 + sk.x) * mk;
    float o1 = (a1 + sk.y) * mk;

    float* op;
    if (m == 0)      op = out + bn * 64 + 2 * j;
    else if (m < 4)  op = out + OUT1_OFF + (bn * 3 + (m - 1)) * 64 + 2 * j;
    else             op = out + OUT2_OFF + (bn * 5 + (m - 4)) * 64 + 2 * j;
    *(float2*)op = make_float2(o0, o1);
}

// ---------------------------------------------------------------------------
extern "C" void kernel_launch(void* const* d_in, const int* in_sizes, int n_in,
                              void* d_out, int out_size) {
    const float* x0     = (const float*)d_in[0];
    const float* x1     = (const float*)d_in[1];
    const float* x2     = (const float*)d_in[2];
    const float* points = (const float*)d_in[3];
    const int*   pidx   = (const int*)  d_in[4];
    const float* mask   = (const float*)d_in[5];
    const float* Wc0    = (const float*)d_in[6];
    const float* Wc1    = (const float*)d_in[7];
    const float* Wc2    = (const float*)d_in[8];
    const float* Wv0    = (const float*)d_in[9];
    const float* Wv1    = (const float*)d_in[10];
    const float* Wv2    = (const float*)d_in[11];
    const float* Ws0    = (const float*)d_in[12];
    const float* Ws1    = (const float*)d_in[13];
    const float* Ws2    = (const float*)d_in[14];
    float* out = (float*)d_out;

    const int smemA = 3 * 64 * ASTR * sizeof(float);   // 52224 B
    cudaFuncSetAttribute(kernelA, cudaFuncAttributeMaxDynamicSharedMemorySize, smemA);

    kernelM<<<12, 256>>>(Wc0, Wc1, Wc2, Wv0, Wv1, Wv2);
    kernelA<<<2304, 256, smemA>>>(x0, x1, x2, mask, Ws0, Ws1, Ws2);
    kernelB<<<16384, 288>>>(points, pidx, mask, out);
}